// round 15
// baseline (speedup 1.0000x reference)
#include <cuda_runtime.h>

// Multi-class hinge (Crammer-Singer) loss, summed over batch.
// outputs: [N, C] fp32, labels: [N] int32, out: scalar fp32.
//
// sum_{i,j != y_i} max(outputs[i,j] - outputs[i,y_i] + 1, 0)
// The j == y_i term contributes exactly 1.0: sum over all j, subtract 1/row.
//
// FINAL — best of 10 measured structural variants across 14 rounds.
// Kernel 40.35-41.25us @ ~6.6-6.8 TB/s, which is the path-independent LTS
// fabric cap (~6300 B/cyc) for this chip; DRAM spec (8 TB/s) is not the
// binding roof. Measured map:
//   per-thread load depth: 2-deep=55us, 4-deep=40.35us (best), 8-deep=61us
//   persistent grid / prefetch / 2-rows-per-CTA / fused ticket epilogue:
//     all measured slower
//   .cs streaming hints: neutral;  memset vs zero-kernel prologue: identical
// Structure:
//   - one CTA per row, 16384 x 256 threads, 4 x float4 per thread
//   - ground-truth value published from the owning thread's registers via
//     smem broadcast (no dependent label->gather LDG on the critical path)
//   - warp shuffle + smem block reduce, one atomicAdd (REDG) per CTA
//     (atomic serialization ~14k cyc, fully hidden under the 44k-cyc stream)

static constexpr int C_DIM   = 4096;
static constexpr int THREADS = 256;          // 4096 / (4*256) = 4 float4 per thread

__global__ void zero_out_kernel(float* out) {
    if (threadIdx.x == 0) out[0] = 0.0f;
}

__global__ __launch_bounds__(THREADS) void hinge_loss_kernel(
    const float* __restrict__ outputs,
    const int* __restrict__ labels,
    float* __restrict__ out)
{
    const int row = blockIdx.x;
    const int tid = threadIdx.x;
    const float4* rowp =
        reinterpret_cast<const float4*>(outputs + (size_t)row * C_DIM);

    // All five loads below are independent — issue together.
    const int lab = __ldg(labels + row);
    float4 v0 = rowp[tid];
    float4 v1 = rowp[tid + THREADS];
    float4 v2 = rowp[tid + 2 * THREADS];
    float4 v3 = rowp[tid + 3 * THREADS];

    // Broadcast the ground-truth value from the owning thread's registers.
    __shared__ float sg;
    const int f = lab >> 2;                   // float4 index within the row
    if (tid == (f & (THREADS - 1))) {
        const int chunk = f >> 8;             // which of v0..v3
        float4 v = (chunk == 0) ? v0 : (chunk == 1) ? v1 : (chunk == 2) ? v2 : v3;
        const float* e = reinterpret_cast<const float*>(&v);
        sg = e[lab & 3];
    }
    __syncthreads();
    const float t = 1.0f - sg;                // margin = max(o + t, 0)

    float s = 0.0f;
    s += fmaxf(v0.x + t, 0.0f); s += fmaxf(v0.y + t, 0.0f);
    s += fmaxf(v0.z + t, 0.0f); s += fmaxf(v0.w + t, 0.0f);
    s += fmaxf(v1.x + t, 0.0f); s += fmaxf(v1.y + t, 0.0f);
    s += fmaxf(v1.z + t, 0.0f); s += fmaxf(v1.w + t, 0.0f);
    s += fmaxf(v2.x + t, 0.0f); s += fmaxf(v2.y + t, 0.0f);
    s += fmaxf(v2.z + t, 0.0f); s += fmaxf(v2.w + t, 0.0f);
    s += fmaxf(v3.x + t, 0.0f); s += fmaxf(v3.y + t, 0.0f);
    s += fmaxf(v3.z + t, 0.0f); s += fmaxf(v3.w + t, 0.0f);

    // warp reduce
    #pragma unroll
    for (int o = 16; o > 0; o >>= 1)
        s += __shfl_xor_sync(0xFFFFFFFFu, s, o);

    __shared__ float ws[THREADS / 32];
    if ((tid & 31) == 0) ws[tid >> 5] = s;
    __syncthreads();

    if (tid == 0) {
        float v = ws[0];
        #pragma unroll
        for (int w = 1; w < THREADS / 32; w++) v += ws[w];
        // subtract the j == label contribution (exactly 1.0)
        atomicAdd(out, v - 1.0f);
    }
}

extern "C" void kernel_launch(void* const* d_in, const int* in_sizes, int n_in,
                              void* d_out, int out_size) {
    const float* outputs = (const float*)d_in[0];
    const int* labels = (const int*)d_in[1];
    float* out = (float*)d_out;

    const int N = in_sizes[1];          // 16384 labels

    zero_out_kernel<<<1, 32>>>(out);
    hinge_loss_kernel<<<N, THREADS>>>(outputs, labels, out);
}

// round 16
// speedup vs baseline: 1.0988x; 1.0988x over previous
#include <cuda_runtime.h>

// Multi-class hinge (Crammer-Singer) loss, summed over batch.
// outputs: [N, C] fp32, labels: [N] int32, out: scalar fp32.
//
// sum_{i,j != y_i} max(outputs[i,j] - outputs[i,y_i] + 1, 0)
// The j == y_i term contributes exactly 1.0: sum over all j, subtract 1/row.
//
// FINAL — best of 10 measured structural variants across 15 rounds.
// Kernel 40.35-41.25us @ ~6.6-6.8 TB/s on normal clock draws = the
// path-independent LTS fabric cap (~6300 B/cyc); DRAM spec (8 TB/s) is not
// the binding roof. R15's 45.4us on this same binary was a DVFS/clock draw
// (issue% scaled inversely with GB/s; identical SASS). Measured map:
//   per-thread load depth: 2-deep=55us, 4-deep=40.35us (best), 8-deep=61us
//   persistent grid / prefetch / 2-rows-per-CTA / fused ticket epilogue:
//     all measured slower
//   .cs streaming hints: neutral;  memset vs zero-kernel prologue: identical
// Structure:
//   - one CTA per row, 16384 x 256 threads, 4 x float4 per thread
//   - ground-truth value published from the owning thread's registers via
//     smem broadcast (no dependent label->gather LDG on the critical path)
//   - warp shuffle + smem block reduce, one atomicAdd (REDG) per CTA

static constexpr int C_DIM   = 4096;
static constexpr int THREADS = 256;          // 4096 / (4*256) = 4 float4 per thread

__global__ void zero_out_kernel(float* out) {
    if (threadIdx.x == 0) out[0] = 0.0f;
}

__global__ __launch_bounds__(THREADS) void hinge_loss_kernel(
    const float* __restrict__ outputs,
    const int* __restrict__ labels,
    float* __restrict__ out)
{
    const int row = blockIdx.x;
    const int tid = threadIdx.x;
    const float4* rowp =
        reinterpret_cast<const float4*>(outputs + (size_t)row * C_DIM);

    // All five loads below are independent — issue together.
    const int lab = __ldg(labels + row);
    float4 v0 = rowp[tid];
    float4 v1 = rowp[tid + THREADS];
    float4 v2 = rowp[tid + 2 * THREADS];
    float4 v3 = rowp[tid + 3 * THREADS];

    // Broadcast the ground-truth value from the owning thread's registers.
    __shared__ float sg;
    const int f = lab >> 2;                   // float4 index within the row
    if (tid == (f & (THREADS - 1))) {
        const int chunk = f >> 8;             // which of v0..v3
        float4 v = (chunk == 0) ? v0 : (chunk == 1) ? v1 : (chunk == 2) ? v2 : v3;
        const float* e = reinterpret_cast<const float*>(&v);
        sg = e[lab & 3];
    }
    __syncthreads();
    const float t = 1.0f - sg;                // margin = max(o + t, 0)

    float s = 0.0f;
    s += fmaxf(v0.x + t, 0.0f); s += fmaxf(v0.y + t, 0.0f);
    s += fmaxf(v0.z + t, 0.0f); s += fmaxf(v0.w + t, 0.0f);
    s += fmaxf(v1.x + t, 0.0f); s += fmaxf(v1.y + t, 0.0f);
    s += fmaxf(v1.z + t, 0.0f); s += fmaxf(v1.w + t, 0.0f);
    s += fmaxf(v2.x + t, 0.0f); s += fmaxf(v2.y + t, 0.0f);
    s += fmaxf(v2.z + t, 0.0f); s += fmaxf(v2.w + t, 0.0f);
    s += fmaxf(v3.x + t, 0.0f); s += fmaxf(v3.y + t, 0.0f);
    s += fmaxf(v3.z + t, 0.0f); s += fmaxf(v3.w + t, 0.0f);

    // warp reduce
    #pragma unroll
    for (int o = 16; o > 0; o >>= 1)
        s += __shfl_xor_sync(0xFFFFFFFFu, s, o);

    __shared__ float ws[THREADS / 32];
    if ((tid & 31) == 0) ws[tid >> 5] = s;
    __syncthreads();

    if (tid == 0) {
        float v = ws[0];
        #pragma unroll
        for (int w = 1; w < THREADS / 32; w++) v += ws[w];
        // subtract the j == label contribution (exactly 1.0)
        atomicAdd(out, v - 1.0f);
    }
}

extern "C" void kernel_launch(void* const* d_in, const int* in_sizes, int n_in,
                              void* d_out, int out_size) {
    const float* outputs = (const float*)d_in[0];
    const int* labels = (const int*)d_in[1];
    float* out = (float*)d_out;

    const int N = in_sizes[1];          // 16384 labels

    zero_out_kernel<<<1, 32>>>(out);
    hinge_loss_kernel<<<N, THREADS>>>(outputs, labels, out);
}